// round 8
// baseline (speedup 1.0000x reference)
#include <cuda_runtime.h>
#include <math.h>

#define SEQ 2048
#define BAT 128
#define INP 128
#define HID 128
#define GATES 512   // 4*HID

// 512 MB scratch for the precomputed input contribution xg[s][b][g]
__device__ float g_xg[(size_t)SEQ * BAT * GATES];

// ---------------------------------------------------------------------------
// Packed fp32x2 helpers (Blackwell).
// ---------------------------------------------------------------------------
__device__ __forceinline__ void fma2(unsigned long long& d,
                                     unsigned long long a,
                                     unsigned long long b) {
    asm("fma.rn.f32x2 %0, %1, %2, %0;" : "+l"(d) : "l"(a), "l"(b));
}
__device__ __forceinline__ float2 unpack2(unsigned long long v) {
    float2 r;
    asm("mov.b64 {%0, %1}, %2;" : "=f"(r.x), "=f"(r.y) : "l"(v));
    return r;
}
__device__ __forceinline__ unsigned long long dup2(float v) {
    unsigned long long r;
    asm("mov.b64 %0, {%1, %1};" : "=l"(r) : "f"(v));
    return r;
}

// ---------------------------------------------------------------------------
// Kernel A: xg[m][g] = sum_k x[m][k] * V[g][k] + b[g] + b2[g]
// (unchanged from round 7 — measured ~894 us, conflict-free, FMA-bound)
// ---------------------------------------------------------------------------
__global__ __launch_bounds__(512, 1) void xg_kernel(
    const float* __restrict__ x, const float* __restrict__ V,
    const float* __restrict__ b1, const float* __restrict__ b2,
    float* __restrict__ xg)
{
    extern __shared__ unsigned char smraw[];
    float* As = reinterpret_cast<float*>(smraw);   // [128k][128m] 64 KB
    float* Bs = As + 128 * 128;                    // [128k][128n] 64 KB

    const int tid = threadIdx.x;
    const int m0 = blockIdx.x * 128;
    const int n0 = blockIdx.y * 128;

#pragma unroll
    for (int i = 0; i < 8; i++) {
        int idx = tid + i * 512;
        int row = idx & 127;
        int k4  = (idx >> 7) << 2;
        float4 v = *reinterpret_cast<const float4*>(x + (size_t)(m0 + row) * INP + k4);
        As[(k4 + 0) * 128 + row] = v.x;
        As[(k4 + 1) * 128 + row] = v.y;
        As[(k4 + 2) * 128 + row] = v.z;
        As[(k4 + 3) * 128 + row] = v.w;
    }
#pragma unroll
    for (int i = 0; i < 8; i++) {
        int idx = tid + i * 512;
        int row = idx & 127;
        int k4  = (idx >> 7) << 2;
        float4 v = *reinterpret_cast<const float4*>(V + (size_t)(n0 + row) * INP + k4);
        Bs[(k4 + 0) * 128 + row] = v.x;
        Bs[(k4 + 1) * 128 + row] = v.y;
        Bs[(k4 + 2) * 128 + row] = v.z;
        Bs[(k4 + 3) * 128 + row] = v.w;
    }
    __syncthreads();

    const int ty = tid >> 5;
    const int mb = ty * 8;
    const int nb = (tid & 31) * 4;

    unsigned long long acc[4][4];
#pragma unroll
    for (int i = 0; i < 4; i++)
#pragma unroll
        for (int j = 0; j < 4; j++) acc[i][j] = 0ULL;

#pragma unroll 8
    for (int k = 0; k < 128; k++) {
        ulonglong2 aA = *reinterpret_cast<const ulonglong2*>(As + k * 128 + mb);
        ulonglong2 aB = *reinterpret_cast<const ulonglong2*>(As + k * 128 + mb + 4);
        float4 bv = *reinterpret_cast<const float4*>(Bs + k * 128 + nb);
        unsigned long long bd0 = dup2(bv.x), bd1 = dup2(bv.y),
                           bd2 = dup2(bv.z), bd3 = dup2(bv.w);
        fma2(acc[0][0], aA.x, bd0); fma2(acc[0][1], aA.x, bd1);
        fma2(acc[0][2], aA.x, bd2); fma2(acc[0][3], aA.x, bd3);
        fma2(acc[1][0], aA.y, bd0); fma2(acc[1][1], aA.y, bd1);
        fma2(acc[1][2], aA.y, bd2); fma2(acc[1][3], aA.y, bd3);
        fma2(acc[2][0], aB.x, bd0); fma2(acc[2][1], aB.x, bd1);
        fma2(acc[2][2], aB.x, bd2); fma2(acc[2][3], aB.x, bd3);
        fma2(acc[3][0], aB.y, bd0); fma2(acc[3][1], aB.y, bd1);
        fma2(acc[3][2], aB.y, bd2); fma2(acc[3][3], aB.y, bd3);
    }

    float bias[4];
#pragma unroll
    for (int n = 0; n < 4; n++)
        bias[n] = b1[n0 + nb + n] + b2[n0 + nb + n];

#pragma unroll
    for (int mp = 0; mp < 4; mp++) {
        float2 c0 = unpack2(acc[mp][0]);
        float2 c1 = unpack2(acc[mp][1]);
        float2 c2 = unpack2(acc[mp][2]);
        float2 c3 = unpack2(acc[mp][3]);
        size_t r0 = (size_t)(m0 + mb + 2 * mp) * GATES + n0 + nb;
        *reinterpret_cast<float4*>(xg + r0) =
            make_float4(c0.x + bias[0], c1.x + bias[1], c2.x + bias[2], c3.x + bias[3]);
        *reinterpret_cast<float4*>(xg + r0 + GATES) =
            make_float4(c0.y + bias[0], c1.y + bias[1], c2.y + bias[2], c3.y + bias[3]);
    }
}

// ---------------------------------------------------------------------------
// Kernel B: recurrence, k-split-4 gate-fused layout.
// One CTA per batch element, 512 threads.
// Thread t: unit j = t>>2, k-quarter kq = t&3 (k in [kq*32, kq*32+32)).
// Each thread accumulates partials for ALL FOUR gates (i,f,g,o) of unit j
// over its 32 k-values -> h-LDS is only 8 x LDS.128 per thread per step.
// Quad butterfly (shfl_xor 1,2) completes all 4 gates in every lane; the
// c/h update then happens thread-locally (no gate-exchange shfls).
// Weights/thread: 4 gates x 32 k = 128 floats: 80 in regs (wr[40] u64),
// 48 in smem (WqS[12][512], 96 KB, pre-permuted, conflict-free LDS.128).
// Double-buffered h, ONE __syncthreads per step, r4 (libm) activations.
// ---------------------------------------------------------------------------
__global__ __launch_bounds__(512, 1) void lstm_rec_kernel(
    const float* __restrict__ xg, const float* __restrict__ W,
    float* __restrict__ out)
{
    extern __shared__ unsigned char smraw[];
    ulonglong2* WqS = reinterpret_cast<ulonglong2*>(smraw);        // [12][512] = 96 KB
    float* hs = reinterpret_cast<float*>(smraw + 12 * 512 * 16);   // [2][128]

    const int t   = threadIdx.x;
    const int bat = blockIdx.x;
    const int j   = t >> 2;             // hidden unit
    const int kq  = t & 3;              // k-quarter

    // Register weights: gate r, k-local [0,20): wr[r*10 + q] = {W[r*128+j][kq*32+2q], +1}
    unsigned long long wr[40];
#pragma unroll
    for (int r = 0; r < 4; r++) {
        const unsigned long long* Wrow = reinterpret_cast<const unsigned long long*>(
            W + (size_t)(r * HID + j) * INP + kq * 32);
#pragma unroll
        for (int q = 0; q < 10; q++) wr[r * 10 + q] = Wrow[q];
    }

    // Pre-permuted smem weights: slot c = r*3+cc holds, for each thread tt,
    // W[r*128 + (tt>>2)][(tt&3)*32 + 20 + 4*cc .. +3]
#pragma unroll
    for (int c = 0; c < 12; c++) {
        int r  = c / 3;
        int cc = c % 3;
        WqS[c * 512 + t] = *reinterpret_cast<const ulonglong2*>(
            W + (size_t)(r * HID + (t >> 2)) * INP + (t & 3) * 32 + 20 + cc * 4);
    }
    if (t < HID) hs[t] = 0.0f;
    __syncthreads();

    // xg addresses for this thread's 4 gate rows
    float c_st = 0.0f, h_st = 0.0f;
    float xgc[4];
    {
        size_t base = (size_t)bat * GATES;
#pragma unroll
        for (int r = 0; r < 4; r++) xgc[r] = xg[base + r * HID + j];
    }

    for (int s = 0; s < SEQ; s++) {
        float xgn[4];
        if (s + 1 < SEQ) {
            size_t base = ((size_t)(s + 1) * BAT + bat) * GATES;
#pragma unroll
            for (int r = 0; r < 4; r++) xgn[r] = xg[base + r * HID + j];
        } else {
#pragma unroll
            for (int r = 0; r < 4; r++) xgn[r] = 0.0f;
        }

        // this thread's k-quarter of h: 8 ulonglong2 chunks
        const ulonglong2* h2 =
            reinterpret_cast<const ulonglong2*>(hs + (s & 1) * HID) + kq * 8;

        unsigned long long acc[4] = {0ULL, 0ULL, 0ULL, 0ULL};
        // k-local [0,20): register weights (chunks 0..4)
#pragma unroll
        for (int q = 0; q < 5; q++) {
            ulonglong2 hv = h2[q];
#pragma unroll
            for (int r = 0; r < 4; r++) fma2(acc[r], hv.x, wr[r * 10 + 2 * q]);
#pragma unroll
            for (int r = 0; r < 4; r++) fma2(acc[r], hv.y, wr[r * 10 + 2 * q + 1]);
        }
        // k-local [20,32): smem weights (chunks 5..7)
#pragma unroll
        for (int cc = 0; cc < 3; cc++) {
            ulonglong2 hv = h2[5 + cc];
#pragma unroll
            for (int r = 0; r < 4; r++) {
                ulonglong2 wv = WqS[(r * 3 + cc) * 512 + t];
                fma2(acc[r], hv.x, wv.x);
                fma2(acc[r], hv.y, wv.y);
            }
        }

        // horizontal + quad butterfly: every lane ends with all 4 full gates
        float p[4];
#pragma unroll
        for (int r = 0; r < 4; r++) {
            float2 u = unpack2(acc[r]);
            p[r] = u.x + u.y;
        }
#pragma unroll
        for (int r = 0; r < 4; r++) p[r] += __shfl_xor_sync(0xffffffffu, p[r], 1);
#pragma unroll
        for (int r = 0; r < 4; r++) p[r] += __shfl_xor_sync(0xffffffffu, p[r], 2);

        float gi = p[0] + xgc[0];
        float gf = p[1] + xgc[1];
        float gg = p[2] + xgc[2];
        float go = p[3] + xgc[3];
#pragma unroll
        for (int r = 0; r < 4; r++) xgc[r] = xgn[r];

        float iv = 1.0f / (1.0f + __expf(-gi));
        float fv = 1.0f / (1.0f + __expf(-gf));
        float gv = tanhf(gg);
        float ov = 1.0f / (1.0f + __expf(-go));

        c_st = fv * c_st + iv * gv;
        h_st = ov * tanhf(c_st);

        if (kq == 0) hs[((s + 1) & 1) * HID + j] = h_st;
        if (kq == 1) out[((size_t)s * BAT + bat) * HID + j] = h_st;
        __syncthreads();
    }

    if (kq == 0) {
        size_t off = (size_t)SEQ * BAT * HID;
        out[off + (size_t)bat * HID + j] = h_st;                        // h_T
    }
    if (kq == 1) {
        size_t off = (size_t)SEQ * BAT * HID;
        out[off + (size_t)BAT * HID + (size_t)bat * HID + j] = c_st;    // c_T
    }
}

// ---------------------------------------------------------------------------
extern "C" void kernel_launch(void* const* d_in, const int* in_sizes, int n_in,
                              void* d_out, int out_size) {
    (void)in_sizes; (void)n_in; (void)out_size;
    const float* x  = (const float*)d_in[0];
    const float* V  = (const float*)d_in[1];
    const float* W  = (const float*)d_in[2];
    const float* b  = (const float*)d_in[3];
    const float* b2 = (const float*)d_in[4];
    float* out = (float*)d_out;

    float* xg = nullptr;
    cudaGetSymbolAddress((void**)&xg, g_xg);

    cudaFuncSetAttribute(xg_kernel, cudaFuncAttributeMaxDynamicSharedMemorySize,
                         128 * 1024);
    const int smemB = 12 * 512 * 16 + 2 * HID * 4 + 256;
    cudaFuncSetAttribute(lstm_rec_kernel, cudaFuncAttributeMaxDynamicSharedMemorySize,
                         smemB);

    dim3 gridA(SEQ * BAT / 128, GATES / 128);
    xg_kernel<<<gridA, 512, 128 * 1024>>>(x, V, b, b2, xg);
    lstm_rec_kernel<<<BAT, 512, smemB>>>(xg, W, out);
}

// round 9
// speedup vs baseline: 1.4361x; 1.4361x over previous
#include <cuda_runtime.h>
#include <math.h>

#define SEQ 2048
#define BAT 128
#define INP 128
#define HID 128
#define GATES 512   // 4*HID

// 512 MB scratch for the precomputed input contribution xg[s][b][g]
__device__ float g_xg[(size_t)SEQ * BAT * GATES];

// ---------------------------------------------------------------------------
// Packed fp32x2 helpers (Blackwell).
// ---------------------------------------------------------------------------
__device__ __forceinline__ void fma2(unsigned long long& d,
                                     unsigned long long a,
                                     unsigned long long b) {
    asm("fma.rn.f32x2 %0, %1, %2, %0;" : "+l"(d) : "l"(a), "l"(b));
}
__device__ __forceinline__ float2 unpack2(unsigned long long v) {
    float2 r;
    asm("mov.b64 {%0, %1}, %2;" : "=f"(r.x), "=f"(r.y) : "l"(v));
    return r;
}
__device__ __forceinline__ unsigned long long dup2(float v) {
    unsigned long long r;
    asm("mov.b64 %0, {%1, %1};" : "=l"(r) : "f"(v));
    return r;
}

// ---------------------------------------------------------------------------
// Kernel A: xg[m][g] = sum_k x[m][k] * V[g][k] + b[g] + b2[g]
// M = 262144, N = 512, K = 128 (single K tile).
// CTA tile 128m x 128n, 512 threads, per-thread 8m x 4n.
// A via warp-broadcast LDS.128, B via one consecutive float4 per lane
// (conflict-free). Accumulators packed along m (32 regs).
// Measured ~884 us in round 8 — unchanged.
// ---------------------------------------------------------------------------
__global__ __launch_bounds__(512, 1) void xg_kernel(
    const float* __restrict__ x, const float* __restrict__ V,
    const float* __restrict__ b1, const float* __restrict__ b2,
    float* __restrict__ xg)
{
    extern __shared__ unsigned char smraw[];
    float* As = reinterpret_cast<float*>(smraw);   // [128k][128m] 64 KB
    float* Bs = As + 128 * 128;                    // [128k][128n] 64 KB

    const int tid = threadIdx.x;
    const int m0 = blockIdx.x * 128;
    const int n0 = blockIdx.y * 128;

#pragma unroll
    for (int i = 0; i < 8; i++) {
        int idx = tid + i * 512;
        int row = idx & 127;
        int k4  = (idx >> 7) << 2;
        float4 v = *reinterpret_cast<const float4*>(x + (size_t)(m0 + row) * INP + k4);
        As[(k4 + 0) * 128 + row] = v.x;
        As[(k4 + 1) * 128 + row] = v.y;
        As[(k4 + 2) * 128 + row] = v.z;
        As[(k4 + 3) * 128 + row] = v.w;
    }
#pragma unroll
    for (int i = 0; i < 8; i++) {
        int idx = tid + i * 512;
        int row = idx & 127;
        int k4  = (idx >> 7) << 2;
        float4 v = *reinterpret_cast<const float4*>(V + (size_t)(n0 + row) * INP + k4);
        Bs[(k4 + 0) * 128 + row] = v.x;
        Bs[(k4 + 1) * 128 + row] = v.y;
        Bs[(k4 + 2) * 128 + row] = v.z;
        Bs[(k4 + 3) * 128 + row] = v.w;
    }
    __syncthreads();

    const int ty = tid >> 5;
    const int mb = ty * 8;
    const int nb = (tid & 31) * 4;

    unsigned long long acc[4][4];
#pragma unroll
    for (int i = 0; i < 4; i++)
#pragma unroll
        for (int j = 0; j < 4; j++) acc[i][j] = 0ULL;

#pragma unroll 8
    for (int k = 0; k < 128; k++) {
        ulonglong2 aA = *reinterpret_cast<const ulonglong2*>(As + k * 128 + mb);
        ulonglong2 aB = *reinterpret_cast<const ulonglong2*>(As + k * 128 + mb + 4);
        float4 bv = *reinterpret_cast<const float4*>(Bs + k * 128 + nb);
        unsigned long long bd0 = dup2(bv.x), bd1 = dup2(bv.y),
                           bd2 = dup2(bv.z), bd3 = dup2(bv.w);
        fma2(acc[0][0], aA.x, bd0); fma2(acc[0][1], aA.x, bd1);
        fma2(acc[0][2], aA.x, bd2); fma2(acc[0][3], aA.x, bd3);
        fma2(acc[1][0], aA.y, bd0); fma2(acc[1][1], aA.y, bd1);
        fma2(acc[1][2], aA.y, bd2); fma2(acc[1][3], aA.y, bd3);
        fma2(acc[2][0], aB.x, bd0); fma2(acc[2][1], aB.x, bd1);
        fma2(acc[2][2], aB.x, bd2); fma2(acc[2][3], aB.x, bd3);
        fma2(acc[3][0], aB.y, bd0); fma2(acc[3][1], aB.y, bd1);
        fma2(acc[3][2], aB.y, bd2); fma2(acc[3][3], aB.y, bd3);
    }

    float bias[4];
#pragma unroll
    for (int n = 0; n < 4; n++)
        bias[n] = b1[n0 + nb + n] + b2[n0 + nb + n];

#pragma unroll
    for (int mp = 0; mp < 4; mp++) {
        float2 c0 = unpack2(acc[mp][0]);
        float2 c1 = unpack2(acc[mp][1]);
        float2 c2 = unpack2(acc[mp][2]);
        float2 c3 = unpack2(acc[mp][3]);
        size_t r0 = (size_t)(m0 + mb + 2 * mp) * GATES + n0 + nb;
        *reinterpret_cast<float4*>(xg + r0) =
            make_float4(c0.x + bias[0], c1.x + bias[1], c2.x + bias[2], c3.x + bias[3]);
        *reinterpret_cast<float4*>(xg + r0 + GATES) =
            make_float4(c0.y + bias[0], c1.y + bias[1], c2.y + bias[2], c3.y + bias[3]);
    }
}

// ---------------------------------------------------------------------------
// Kernel B: recurrence — ROUND-4 SOURCE VERBATIM (measured 2433 us).
// One CTA per batch element, 512 threads.
// Thread t: unit j = t>>2, gate grp = t&3, gate row g = grp*128+j.
// Quad-shfl gate exchange, ONE __syncthreads per step.
// Weights: W[g][0..95] in regs (48 u64), W[g][96..127] in smem, pre-permuted.
// libm activations (polynomial FFMA path — measured faster than MUFU forms).
// ---------------------------------------------------------------------------
__global__ __launch_bounds__(512, 1) void lstm_rec_kernel(
    const float* __restrict__ xg, const float* __restrict__ W,
    float* __restrict__ out)
{
    extern __shared__ unsigned char smraw[];
    ulonglong2* WqS = reinterpret_cast<ulonglong2*>(smraw);       // [8][512] = 64 KB
    float* hs = reinterpret_cast<float*>(smraw + 8 * 512 * 16);   // [2][128]

    const int t   = threadIdx.x;
    const int bat = blockIdx.x;
    const int j   = t >> 2;
    const int grp = t & 3;
    const int g   = grp * HID + j;      // this thread's gate row
    const int qb  = (t & 31) & ~3;      // quad base lane

    // W[g][0..95] -> 48 u64 registers
    unsigned long long wr[48];
    const unsigned long long* Wrow =
        reinterpret_cast<const unsigned long long*>(W + (size_t)g * INP);
#pragma unroll
    for (int q = 0; q < 48; q++) wr[q] = Wrow[q];

    // Pre-permuted smem weights: slot tt <- W[gate_of(tt)][96 + 4*kq .. +3]
    for (int idx = t; idx < 8 * 512; idx += 512) {
        int kq = idx >> 9;
        int tt = idx & 511;
        int gt = (tt & 3) * HID + (tt >> 2);    // gate row of thread tt
        WqS[kq * 512 + tt] =
            *reinterpret_cast<const ulonglong2*>(W + (size_t)gt * INP + 96 + kq * 4);
    }
    if (t < HID) { hs[t] = 0.0f; }
    __syncthreads();

    float c = 0.0f, h = 0.0f;
    float xg_cur = xg[(size_t)bat * GATES + g];

    for (int s = 0; s < SEQ; s++) {
        float xg_next = 0.0f;
        if (s + 1 < SEQ)
            xg_next = xg[((size_t)(s + 1) * BAT + bat) * GATES + g];

        const ulonglong2* h2 =
            reinterpret_cast<const ulonglong2*>(hs + (s & 1) * HID);

        unsigned long long a0 = 0ULL, a1 = 0ULL, a2 = 0ULL, a3 = 0ULL;
        // h[0..95] x register weights (24 ulonglong2 h-chunks)
#pragma unroll
        for (int q = 0; q < 24; q += 2) {
            ulonglong2 hA = h2[q];
            ulonglong2 hB = h2[q + 1];
            fma2(a0, hA.x, wr[2 * q + 0]);
            fma2(a1, hA.y, wr[2 * q + 1]);
            fma2(a2, hB.x, wr[2 * q + 2]);
            fma2(a3, hB.y, wr[2 * q + 3]);
        }
        // h[96..127] x smem weights (pre-permuted, conflict-free)
#pragma unroll
        for (int q = 0; q < 8; q++) {
            ulonglong2 hv = h2[24 + q];
            ulonglong2 wv = WqS[q * 512 + t];
            if (q & 1) { fma2(a2, hv.x, wv.x); fma2(a3, hv.y, wv.y); }
            else       { fma2(a0, hv.x, wv.x); fma2(a1, hv.y, wv.y); }
        }
        float2 p0 = unpack2(a0), p1 = unpack2(a1),
               p2 = unpack2(a2), p3 = unpack2(a3);
        float gate = ((p0.x + p0.y) + (p1.x + p1.y)) +
                     ((p2.x + p2.y) + (p3.x + p3.y)) + xg_cur;
        xg_cur = xg_next;

        // own activation: grp 0,1,3 -> sigmoid ; grp 2 -> tanh
        float act = (grp == 2) ? tanhf(gate)
                               : (1.0f / (1.0f + __expf(-gate)));

        float vi = __shfl_sync(0xffffffffu, act, qb + 0);
        float vf = __shfl_sync(0xffffffffu, act, qb + 1);
        float vg = __shfl_sync(0xffffffffu, act, qb + 2);
        float vo = __shfl_sync(0xffffffffu, act, qb + 3);

        c = vf * c + vi * vg;
        h = vo * tanhf(c);

        if (grp == 0) hs[((s + 1) & 1) * HID + j] = h;
        if (grp == 1) out[((size_t)s * BAT + bat) * HID + j] = h;
        __syncthreads();
    }

    if (grp == 0) {
        size_t off = (size_t)SEQ * BAT * HID;
        out[off + (size_t)bat * HID + j] = h;                           // h_T
        out[off + (size_t)BAT * HID + (size_t)bat * HID + j] = c;       // c_T
    }
}

// ---------------------------------------------------------------------------
extern "C" void kernel_launch(void* const* d_in, const int* in_sizes, int n_in,
                              void* d_out, int out_size) {
    (void)in_sizes; (void)n_in; (void)out_size;
    const float* x  = (const float*)d_in[0];
    const float* V  = (const float*)d_in[1];
    const float* W  = (const float*)d_in[2];
    const float* b  = (const float*)d_in[3];
    const float* b2 = (const float*)d_in[4];
    float* out = (float*)d_out;

    float* xg = nullptr;
    cudaGetSymbolAddress((void**)&xg, g_xg);

    cudaFuncSetAttribute(xg_kernel, cudaFuncAttributeMaxDynamicSharedMemorySize,
                         128 * 1024);
    const int smemB = 8 * 512 * 16 + 2 * HID * 4 + 256;
    cudaFuncSetAttribute(lstm_rec_kernel, cudaFuncAttributeMaxDynamicSharedMemorySize,
                         smemB);

    dim3 gridA(SEQ * BAT / 128, GATES / 128);
    xg_kernel<<<gridA, 512, 128 * 1024>>>(x, V, b, b2, xg);
    lstm_rec_kernel<<<BAT, 512, smemB>>>(xg, W, out);
}